// round 16
// baseline (speedup 1.0000x reference)
#include <cuda_runtime.h>
#include <cuda_fp16.h>
#include <math.h>
#include <stdint.h>

// Problem constants
#define PB   4
#define PS   2048
#define PH   1024      // hidden = NH*HD
#define PNH  16
#define PHD  64
#define PWH  32        // window half = WIN//2
#define PM   (PB*PS)   // 8192 GEMM rows

// Scratch (allocation-free)
#define SCR_ELEMS (PB*PS*PH)
__device__ float   g_q[SCR_ELEMS];
__device__ float   g_k[SCR_ELEMS];
__device__ float   g_v[SCR_ELEMS];
__device__ __half  g_xh[SCR_ELEMS];      // x as fp16 rows (GEMM A-side)
__device__ __half  g_ah[SCR_ELEMS];      // attn out as fp16 rows (A-side of O-proj)
__device__ uint32_t g_wqp[PH*PH/2];      // W packed [k-pair][n] half2 (B-side)
__device__ uint32_t g_wkp[PH*PH/2];
__device__ uint32_t g_wvp[PH*PH/2];
__device__ uint32_t g_wop[PH*PH/2];

// ---------------------------------------------------------------------------
// Helpers
// ---------------------------------------------------------------------------
__device__ __forceinline__ void mma_f16(float* c, const uint32_t* a,
                                        const uint32_t* b) {
    asm volatile(
        "mma.sync.aligned.m16n8k16.row.col.f32.f16.f16.f32 "
        "{%0,%1,%2,%3}, {%4,%5,%6,%7}, {%8,%9}, {%0,%1,%2,%3};"
        : "+f"(c[0]), "+f"(c[1]), "+f"(c[2]), "+f"(c[3])
        : "r"(a[0]), "r"(a[1]), "r"(a[2]), "r"(a[3]),
          "r"(b[0]), "r"(b[1]));
}

__device__ __forceinline__ uint32_t pack_h2(float lo, float hi) {
    __half2 h = __floats2half2_rn(lo, hi);
    return *(uint32_t*)&h;
}

__device__ __forceinline__ void cp16(void* smem_dst, const void* gmem_src) {
    uint32_t d = (uint32_t)__cvta_generic_to_shared(smem_dst);
    asm volatile("cp.async.ca.shared.global [%0], [%1], 16;\n"
                 :: "r"(d), "l"(gmem_src));
}

// ---------------------------------------------------------------------------
// Pre-passes (RN conversions identical to R15)
// ---------------------------------------------------------------------------
__global__ __launch_bounds__(256) void f32_to_f16_kernel(
    const float* __restrict__ in, __half* __restrict__ out, int n4)
{
    int i = blockIdx.x * 256 + threadIdx.x;
    if (i < n4) {
        float4 v = ((const float4*)in)[i];
        uint2 u;
        u.x = pack_h2(v.x, v.y);
        u.y = pack_h2(v.z, v.w);
        ((uint2*)out)[i] = u;
    }
}

// Wp[kk*1024 + n] = half2(W[2kk][n], W[2kk+1][n])
__global__ __launch_bounds__(256) void pack_w_kernel(
    const float* __restrict__ W, uint32_t* __restrict__ Wp)
{
    int idx = blockIdx.x * 256 + threadIdx.x;   // 512*1024 total
    int kk = idx >> 10, n = idx & 1023;
    float a = W[(size_t)(2 * kk) * PH + n];
    float b = W[(size_t)(2 * kk + 1) * PH + n];
    Wp[(size_t)kk * PH + n] = pack_h2(a, b);
}

// ---------------------------------------------------------------------------
// GEMM v5 (fp16 mma m16n8k16, cp.async 2-stage) — unchanged from R15 (76us)
// ---------------------------------------------------------------------------
#define GK 1024
#define GN 1024
#define SAH2 20
#define SBH2 136
#define NIT 32

__global__ __launch_bounds__(256) void gemm_f16_db(
    const __half* __restrict__ A, const uint32_t* __restrict__ Wp,
    const float* __restrict__ bias, float* __restrict__ C)
{
    __shared__ uint32_t As2[2][128 * SAH2];  // 2 x 10240 B
    __shared__ uint32_t Bs2[2][16 * SBH2];   // 2 x  8704 B

    const int tid = threadIdx.x;
    const int m0 = blockIdx.y * 128;
    const int n0 = blockIdx.x * 128;
    const int warp = tid >> 5;
    const int lane = tid & 31;
    const int g  = lane >> 2;
    const int tg = lane & 3;
    const int wm = (warp & 1) * 64;
    const int wn = (warp >> 1) * 32;

    float acc[4][4][4];
    #pragma unroll
    for (int mi = 0; mi < 4; mi++)
        #pragma unroll
        for (int ni = 0; ni < 4; ni++)
            #pragma unroll
            for (int r = 0; r < 4; r++) acc[mi][ni][r] = 0.f;

    const __half* Ab = A + (size_t)m0 * GK;

    auto load_stage = [&](int s, int k0) {
        #pragma unroll
        for (int i = 0; i < 2; i++) {
            int id = tid + (i << 8);
            int r = id >> 2, c = id & 3;
            cp16(&As2[s][r * SAH2 + c * 4],
                 Ab + (size_t)r * GK + k0 + c * 8);
        }
        #pragma unroll
        for (int i = 0; i < 2; i++) {
            int id = tid + (i << 8);
            int kk = id >> 5, c = id & 31;
            cp16(&Bs2[s][kk * SBH2 + c * 4],
                 Wp + (size_t)((k0 >> 1) + kk) * GN + n0 + c * 4);
        }
        asm volatile("cp.async.commit_group;\n" ::: "memory");
    };

    load_stage(0, 0);

    for (int it = 0; it < NIT; it++) {
        if (it + 1 < NIT) {
            load_stage((it + 1) & 1, (it + 1) * 32);
            asm volatile("cp.async.wait_group 1;\n" ::: "memory");
        } else {
            asm volatile("cp.async.wait_group 0;\n" ::: "memory");
        }
        __syncthreads();

        const int s = it & 1;
        #pragma unroll
        for (int ks = 0; ks < 2; ks++) {
            const int kb = ks * 8;
            uint32_t af[4][4], bf[4][2];
            #pragma unroll
            for (int mi = 0; mi < 4; mi++) {
                const int mr = wm + mi * 16 + g;
                af[mi][0] = As2[s][mr * SAH2       + kb + tg];
                af[mi][1] = As2[s][(mr + 8) * SAH2 + kb + tg];
                af[mi][2] = As2[s][mr * SAH2       + kb + tg + 4];
                af[mi][3] = As2[s][(mr + 8) * SAH2 + kb + tg + 4];
            }
            #pragma unroll
            for (int ni = 0; ni < 4; ni++) {
                const int nc = wn + ni * 8 + g;
                bf[ni][0] = Bs2[s][(kb + tg) * SBH2     + nc];
                bf[ni][1] = Bs2[s][(kb + tg + 4) * SBH2 + nc];
            }
            #pragma unroll
            for (int mi = 0; mi < 4; mi++)
                #pragma unroll
                for (int ni = 0; ni < 4; ni++)
                    mma_f16(acc[mi][ni], af[mi], bf[ni]);
        }
        __syncthreads();
    }

    #pragma unroll
    for (int mi = 0; mi < 4; mi++) {
        const int row0 = m0 + wm + mi * 16 + g;
        #pragma unroll
        for (int ni = 0; ni < 4; ni++) {
            const int col = n0 + wn + ni * 8 + tg * 2;
            const float2 bv = *(const float2*)(bias + col);
            float2 o0, o1;
            o0.x = acc[mi][ni][0] + bv.x; o0.y = acc[mi][ni][1] + bv.y;
            o1.x = acc[mi][ni][2] + bv.x; o1.y = acc[mi][ni][3] + bv.y;
            *(float2*)(C + (size_t)row0 * GN + col)       = o0;
            *(float2*)(C + (size_t)(row0 + 8) * GN + col) = o1;
        }
    }
}

// ---------------------------------------------------------------------------
// Banded attention v4: V tile prefetched via cp.async into DYNAMIC smem at
// kernel start, overlapped under the score phase; V pass reads smem (LDS.64,
// conflict-free). Score/softmax math identical to R6/R15.
// ---------------------------------------------------------------------------
#define KSTR 68
#define VT_ROWS 96
#define VS_BYTES (VT_ROWS * KSTR * 4)   // 26112

__global__ __launch_bounds__(256) void attn_kernel(
    const float* __restrict__ q, const float* __restrict__ k,
    const float* __restrict__ v, const int* __restrict__ mask,
    __half* __restrict__ out)
{
    constexpr int QT = 32;
    constexpr int KT = QT + 2 * PWH;  // 96
    __shared__ float Ks[KT * KSTR];
    __shared__ float Qs[QT][PHD];
    __shared__ float Pr4[8][4][68];
    extern __shared__ float Vs[];     // [96][KSTR]

    const int nqt = PS / QT;
    const int blk = blockIdx.x;
    const int qt = blk % nqt;
    const int h  = (blk / nqt) % PNH;
    const int b  = blk / (nqt * PNH);
    const int t0 = qt * QT;
    const int tid = threadIdx.x;
    const size_t base = ((size_t)b * PS) * PH + (size_t)h * PHD;

    // ---- Prefetch V tile (rows t0-32 .. t0+63) via cp.async; OOB -> zeros ----
    for (int idx = tid; idx < VT_ROWS * 16; idx += 256) {
        int u = idx >> 4;           // tile row 0..95
        int c = idx & 15;           // 16B chunk in row
        int jg = t0 - PWH + u;
        float* dst = &Vs[u * KSTR + c * 4];
        if (jg >= 0 && jg < PS) {
            cp16(dst, v + base + (size_t)jg * PH + c * 4);
        } else {
            dst[0] = 0.f; dst[1] = 0.f; dst[2] = 0.f; dst[3] = 0.f;
        }
    }
    asm volatile("cp.async.commit_group;\n" ::: "memory");

    // ---- K and Q tiles (blocking loads, as before) ----
    for (int idx = tid; idx < KT * (PHD / 4); idx += 256) {
        int r  = idx >> 4;
        int c4 = (idx & 15) << 2;
        int jg = t0 - PWH + r;
        float4 kv = make_float4(0.f, 0.f, 0.f, 0.f);
        if (jg >= 0 && jg < PS)
            kv = *(const float4*)(k + base + (size_t)jg * PH + c4);
        *(float4*)(&Ks[r * KSTR + c4]) = kv;
    }
    for (int idx = tid; idx < QT * (PHD / 4); idx += 256) {
        int r  = idx >> 4;
        int c4 = (idx & 15) << 2;
        *(float4*)(&Qs[r][c4]) =
            *(const float4*)(q + base + (size_t)(t0 + r) * PH + c4);
    }
    __syncthreads();

    const int w = tid >> 5, l = tid & 31;
    const float inv_scale = 0.125f;

    #pragma unroll
    for (int qi = 0; qi < 4; qi++) {
        const int ql = 4 * w + qi;
        const int ig = t0 + ql;
        const int j0 = ig - PWH + l;
        const int j1 = j0 + 32;
        const int j2 = ig + PWH;
        const bool v0 = (j0 >= 0) && (j0 < PS) && (mask[b * PS + j0] != 0);
        const bool v1 = (j1 < PS) && (mask[b * PS + j1] != 0);
        const bool v2 = (j2 < PS) && (mask[b * PS + j2] != 0);

        const float4* K0 = (const float4*)(&Ks[(ql + l)      * KSTR]);
        const float4* K1 = (const float4*)(&Ks[(ql + l + 32) * KSTR]);
        const float4* K2 = (const float4*)(&Ks[(ql + 64)     * KSTR]);
        const float4* Qv = (const float4*)(&Qs[ql][0]);

        float s0 = 0.f, s1 = 0.f, s2 = 0.f;
        #pragma unroll
        for (int d4 = 0; d4 < PHD / 4; d4++) {
            float4 qv = Qv[d4];
            float4 a = K0[d4], c = K1[d4], e = K2[d4];
            s0 += qv.x * a.x + qv.y * a.y + qv.z * a.z + qv.w * a.w;
            s1 += qv.x * c.x + qv.y * c.y + qv.z * c.z + qv.w * c.w;
            s2 += qv.x * e.x + qv.y * e.y + qv.z * e.z + qv.w * e.w;
        }
        s0 = v0 ? s0 * inv_scale : -INFINITY;
        s1 = v1 ? s1 * inv_scale : -INFINITY;
        s2 = v2 ? s2 * inv_scale : -INFINITY;

        float m = fmaxf(fmaxf(s0, s1), s2);
        #pragma unroll
        for (int off = 16; off; off >>= 1)
            m = fmaxf(m, __shfl_xor_sync(0xffffffffu, m, off));

        const bool any = (m > -INFINITY);
        float e0 = (v0 && any) ? __expf(s0 - m) : 0.f;
        float e1 = (v1 && any) ? __expf(s1 - m) : 0.f;
        float e2 = (v2 && any) ? __expf(s2 - m) : 0.f;

        float ssum = e0 + e1;
        #pragma unroll
        for (int off = 16; off; off >>= 1)
            ssum += __shfl_xor_sync(0xffffffffu, ssum, off);
        ssum += e2;
        const float inv = any ? (1.0f / ssum) : 0.f;

        #pragma unroll
        for (int r = l; r < 68; r += 32) Pr4[w][qi][r] = 0.f;
        __syncwarp();
        Pr4[w][qi][qi + l]      = e0 * inv;
        Pr4[w][qi][qi + l + 32] = e1 * inv;
        if (l == 0) Pr4[w][qi][qi + 64] = e2 * inv;
        __syncwarp();
    }

    // ---- V pass from prefetched smem tile ----
    asm volatile("cp.async.wait_group 0;\n" ::: "memory");
    __syncthreads();

    float2 a0 = make_float2(0.f, 0.f), a1 = a0, a2 = a0, a3 = a0;
    #pragma unroll 4
    for (int r = 0; r < 68; r++) {
        const float2 vv = *(const float2*)(&Vs[(4 * w + r) * KSTR + 2 * l]);
        const float p0 = Pr4[w][0][r];
        const float p1 = Pr4[w][1][r];
        const float p2 = Pr4[w][2][r];
        const float p3 = Pr4[w][3][r];
        a0.x += p0 * vv.x; a0.y += p0 * vv.y;
        a1.x += p1 * vv.x; a1.y += p1 * vv.y;
        a2.x += p2 * vv.x; a2.y += p2 * vv.y;
        a3.x += p3 * vv.x; a3.y += p3 * vv.y;
    }

    {
        const int ig0 = t0 + 4 * w;
        uint32_t* o = (uint32_t*)(out + base + (size_t)ig0 * PH + 2 * l);
        o[0]          = pack_h2(a0.x, a0.y);
        o[PH / 2]     = pack_h2(a1.x, a1.y);
        o[PH]         = pack_h2(a2.x, a2.y);
        o[3 * PH / 2] = pack_h2(a3.x, a3.y);
    }
}

// ---------------------------------------------------------------------------
extern "C" void kernel_launch(void* const* d_in, const int* in_sizes, int n_in,
                              void* d_out, int out_size)
{
    const float* x    = (const float*)d_in[0];
    const int*   mask = (const int*)  d_in[1];
    const float* Wq   = (const float*)d_in[2];
    const float* bq   = (const float*)d_in[3];
    const float* Wk   = (const float*)d_in[4];
    const float* bk   = (const float*)d_in[5];
    const float* Wv   = (const float*)d_in[6];
    const float* bv   = (const float*)d_in[7];
    const float* Wo   = (const float*)d_in[8];
    const float* bo   = (const float*)d_in[9];
    float* out = (float*)d_out;

    float *qp, *kp, *vp;
    __half *xh, *ah;
    uint32_t *wqp, *wkp, *wvp, *wop;
    cudaGetSymbolAddress((void**)&qp,  g_q);
    cudaGetSymbolAddress((void**)&kp,  g_k);
    cudaGetSymbolAddress((void**)&vp,  g_v);
    cudaGetSymbolAddress((void**)&xh,  g_xh);
    cudaGetSymbolAddress((void**)&ah,  g_ah);
    cudaGetSymbolAddress((void**)&wqp, g_wqp);
    cudaGetSymbolAddress((void**)&wkp, g_wkp);
    cudaGetSymbolAddress((void**)&wvp, g_wvp);
    cudaGetSymbolAddress((void**)&wop, g_wop);

    cudaFuncSetAttribute(attn_kernel,
                         cudaFuncAttributeMaxDynamicSharedMemorySize, VS_BYTES);

    // Pre-passes
    const int nx4 = SCR_ELEMS / 4;
    f32_to_f16_kernel<<<(nx4 + 255) / 256, 256>>>(x, xh, nx4);
    const int nw = PH * PH / 2;
    pack_w_kernel<<<nw / 256, 256>>>(Wq, wqp);
    pack_w_kernel<<<nw / 256, 256>>>(Wk, wkp);
    pack_w_kernel<<<nw / 256, 256>>>(Wv, wvp);
    pack_w_kernel<<<nw / 256, 256>>>(Wo, wop);

    dim3 ggrid(GN / 128, PM / 128);  // (8, 64)
    gemm_f16_db<<<ggrid, 256>>>(xh, wqp, bq, qp);
    gemm_f16_db<<<ggrid, 256>>>(xh, wkp, bk, kp);
    gemm_f16_db<<<ggrid, 256>>>(xh, wvp, bv, vp);

    attn_kernel<<<PB * PNH * (PS / 32), 256, VS_BYTES>>>(qp, kp, vp, mask, ah);

    gemm_f16_db<<<ggrid, 256>>>(ah, wop, bo, out);
}

// round 17
// speedup vs baseline: 1.1337x; 1.1337x over previous
#include <cuda_runtime.h>
#include <cuda_fp16.h>
#include <math.h>
#include <stdint.h>

// Problem constants
#define PB   4
#define PS   2048
#define PH   1024      // hidden = NH*HD
#define PNH  16
#define PHD  64
#define PWH  32        // window half = WIN//2
#define PM   (PB*PS)   // 8192 GEMM rows

// Scratch (allocation-free)
#define SCR_ELEMS (PB*PS*PH)
__device__ float   g_q[SCR_ELEMS];
__device__ float   g_k[SCR_ELEMS];
__device__ float   g_v[SCR_ELEMS];
__device__ __half  g_xh[SCR_ELEMS];      // x as fp16 rows (GEMM A-side)
__device__ __half  g_ah[SCR_ELEMS];      // attn out as fp16 rows (A-side of O-proj)
__device__ uint32_t g_wqp[PH*PH/2];      // W packed [k-pair][n] half2 (B-side)
__device__ uint32_t g_wkp[PH*PH/2];
__device__ uint32_t g_wvp[PH*PH/2];
__device__ uint32_t g_wop[PH*PH/2];

// ---------------------------------------------------------------------------
// Helpers
// ---------------------------------------------------------------------------
__device__ __forceinline__ void mma_f16(float* c, const uint32_t* a,
                                        const uint32_t* b) {
    asm volatile(
        "mma.sync.aligned.m16n8k16.row.col.f32.f16.f16.f32 "
        "{%0,%1,%2,%3}, {%4,%5,%6,%7}, {%8,%9}, {%0,%1,%2,%3};"
        : "+f"(c[0]), "+f"(c[1]), "+f"(c[2]), "+f"(c[3])
        : "r"(a[0]), "r"(a[1]), "r"(a[2]), "r"(a[3]),
          "r"(b[0]), "r"(b[1]));
}

__device__ __forceinline__ uint32_t pack_h2(float lo, float hi) {
    __half2 h = __floats2half2_rn(lo, hi);
    return *(uint32_t*)&h;
}

__device__ __forceinline__ void cp16(void* smem_dst, const void* gmem_src) {
    uint32_t d = (uint32_t)__cvta_generic_to_shared(smem_dst);
    asm volatile("cp.async.ca.shared.global [%0], [%1], 16;\n"
                 :: "r"(d), "l"(gmem_src));
}

// ---------------------------------------------------------------------------
// Pre-passes (unchanged from R15)
// ---------------------------------------------------------------------------
__global__ __launch_bounds__(256) void f32_to_f16_kernel(
    const float* __restrict__ in, __half* __restrict__ out, int n4)
{
    int i = blockIdx.x * 256 + threadIdx.x;
    if (i < n4) {
        float4 v = ((const float4*)in)[i];
        uint2 u;
        u.x = pack_h2(v.x, v.y);
        u.y = pack_h2(v.z, v.w);
        ((uint2*)out)[i] = u;
    }
}

__global__ __launch_bounds__(256) void pack_w_kernel(
    const float* __restrict__ W, uint32_t* __restrict__ Wp)
{
    int idx = blockIdx.x * 256 + threadIdx.x;
    int kk = idx >> 10, n = idx & 1023;
    float a = W[(size_t)(2 * kk) * PH + n];
    float b = W[(size_t)(2 * kk + 1) * PH + n];
    Wp[(size_t)kk * PH + n] = pack_h2(a, b);
}

// ---------------------------------------------------------------------------
// GEMM v5 (fp16 mma m16n8k16, cp.async 2-stage) — unchanged from R15 (~76us)
// ---------------------------------------------------------------------------
#define GK 1024
#define GN 1024
#define SAH2 20
#define SBH2 136
#define NIT 32

__global__ __launch_bounds__(256) void gemm_f16_db(
    const __half* __restrict__ A, const uint32_t* __restrict__ Wp,
    const float* __restrict__ bias, float* __restrict__ C)
{
    __shared__ uint32_t As2[2][128 * SAH2];
    __shared__ uint32_t Bs2[2][16 * SBH2];

    const int tid = threadIdx.x;
    const int m0 = blockIdx.y * 128;
    const int n0 = blockIdx.x * 128;
    const int warp = tid >> 5;
    const int lane = tid & 31;
    const int g  = lane >> 2;
    const int tg = lane & 3;
    const int wm = (warp & 1) * 64;
    const int wn = (warp >> 1) * 32;

    float acc[4][4][4];
    #pragma unroll
    for (int mi = 0; mi < 4; mi++)
        #pragma unroll
        for (int ni = 0; ni < 4; ni++)
            #pragma unroll
            for (int r = 0; r < 4; r++) acc[mi][ni][r] = 0.f;

    const __half* Ab = A + (size_t)m0 * GK;

    auto load_stage = [&](int s, int k0) {
        #pragma unroll
        for (int i = 0; i < 2; i++) {
            int id = tid + (i << 8);
            int r = id >> 2, c = id & 3;
            cp16(&As2[s][r * SAH2 + c * 4],
                 Ab + (size_t)r * GK + k0 + c * 8);
        }
        #pragma unroll
        for (int i = 0; i < 2; i++) {
            int id = tid + (i << 8);
            int kk = id >> 5, c = id & 31;
            cp16(&Bs2[s][kk * SBH2 + c * 4],
                 Wp + (size_t)((k0 >> 1) + kk) * GN + n0 + c * 4);
        }
        asm volatile("cp.async.commit_group;\n" ::: "memory");
    };

    load_stage(0, 0);

    for (int it = 0; it < NIT; it++) {
        if (it + 1 < NIT) {
            load_stage((it + 1) & 1, (it + 1) * 32);
            asm volatile("cp.async.wait_group 1;\n" ::: "memory");
        } else {
            asm volatile("cp.async.wait_group 0;\n" ::: "memory");
        }
        __syncthreads();

        const int s = it & 1;
        #pragma unroll
        for (int ks = 0; ks < 2; ks++) {
            const int kb = ks * 8;
            uint32_t af[4][4], bf[4][2];
            #pragma unroll
            for (int mi = 0; mi < 4; mi++) {
                const int mr = wm + mi * 16 + g;
                af[mi][0] = As2[s][mr * SAH2       + kb + tg];
                af[mi][1] = As2[s][(mr + 8) * SAH2 + kb + tg];
                af[mi][2] = As2[s][mr * SAH2       + kb + tg + 4];
                af[mi][3] = As2[s][(mr + 8) * SAH2 + kb + tg + 4];
            }
            #pragma unroll
            for (int ni = 0; ni < 4; ni++) {
                const int nc = wn + ni * 8 + g;
                bf[ni][0] = Bs2[s][(kb + tg) * SBH2     + nc];
                bf[ni][1] = Bs2[s][(kb + tg + 4) * SBH2 + nc];
            }
            #pragma unroll
            for (int mi = 0; mi < 4; mi++)
                #pragma unroll
                for (int ni = 0; ni < 4; ni++)
                    mma_f16(acc[mi][ni], af[mi], bf[ni]);
        }
        __syncthreads();
    }

    #pragma unroll
    for (int mi = 0; mi < 4; mi++) {
        const int row0 = m0 + wm + mi * 16 + g;
        #pragma unroll
        for (int ni = 0; ni < 4; ni++) {
            const int col = n0 + wn + ni * 8 + tg * 2;
            const float2 bv = *(const float2*)(bias + col);
            float2 o0, o1;
            o0.x = acc[mi][ni][0] + bv.x; o0.y = acc[mi][ni][1] + bv.y;
            o1.x = acc[mi][ni][2] + bv.x; o1.y = acc[mi][ni][3] + bv.y;
            *(float2*)(C + (size_t)row0 * GN + col)       = o0;
            *(float2*)(C + (size_t)(row0 + 8) * GN + col) = o1;
        }
    }
}

// ---------------------------------------------------------------------------
// Banded attention v5: score phase on fp16 tensor cores.
// S(32x96) = Q(32x64) @ K^T via m16n8k16 (fragment layouts identical to the
// proven GEMM). Softmax/mask and fp32 V pass unchanged from R15.
// ---------------------------------------------------------------------------
#define KSTR 68
#define SQ2  36    // Qs2 stride (half2): A-frag banks 4g+tg bijective
#define SK2  104   // Ks2 stride (half2): 104%32==8 -> B-frag banks 8tg+g bijective
#define SSV  100   // Sv stride (floats)

__global__ __launch_bounds__(256) void attn_kernel(
    const float* __restrict__ q, const float* __restrict__ k,
    const float* __restrict__ v, const int* __restrict__ mask,
    __half* __restrict__ out)
{
    constexpr int QT = 32;            // queries per block
    constexpr int KT = 96;            // band rows
    __shared__ uint32_t Qs2[QT * SQ2];   //  4608 B  [row][dpair] half2
    __shared__ uint32_t Ks2[32 * SK2];   // 13312 B  [dpair][key] half2
    __shared__ float    Sv[QT * SSV];    // 12800 B  scores
    __shared__ float    Pr4[8][4][68];   //  8704 B

    const int nqt = PS / QT;
    const int blk = blockIdx.x;
    const int qt = blk % nqt;
    const int h  = (blk / nqt) % PNH;
    const int b  = blk / (nqt * PNH);
    const int t0 = qt * QT;
    const int tid = threadIdx.x;
    const size_t base = ((size_t)b * PS) * PH + (size_t)h * PHD;

    // ---- Pack K band tile -> Ks2[dpair][key], fp16, OOB rows = 0 ----
    for (int idx = tid; idx < KT * 32; idx += 256) {
        int key = idx >> 5;           // 0..95
        int dd  = idx & 31;           // dpair 0..31
        int jg = t0 - PWH + key;
        float2 kv = make_float2(0.f, 0.f);
        if (jg >= 0 && jg < PS)
            kv = *(const float2*)(k + base + (size_t)jg * PH + 2 * dd);
        Ks2[dd * SK2 + key] = pack_h2(kv.x, kv.y);
    }
    // ---- Pack Q tile -> Qs2[row][dpair], fp16 ----
    for (int idx = tid; idx < QT * 32; idx += 256) {
        int row = idx >> 5;
        int dd  = idx & 31;
        float2 qv = *(const float2*)(q + base + (size_t)(t0 + row) * PH + 2 * dd);
        Qs2[row * SQ2 + dd] = pack_h2(qv.x, qv.y);
    }
    __syncthreads();

    const int w = tid >> 5, l = tid & 31;
    const int g  = l >> 2;
    const int tg = l & 3;

    // ---- Score mma: warp w -> m-tile (w&1), key-group (w>>2)... 2x4 split ----
    {
        const int mt = w & 1;            // 16-query tile
        const int ng = w >> 1;           // 24-key group (4 groups)
        float sacc[3][4];
        #pragma unroll
        for (int ni = 0; ni < 3; ni++)
            #pragma unroll
            for (int r = 0; r < 4; r++) sacc[ni][r] = 0.f;

        #pragma unroll
        for (int ks = 0; ks < 4; ks++) {
            const int kb = ks * 8;
            uint32_t af[4];
            const int mr = mt * 16 + g;
            af[0] = Qs2[mr * SQ2       + kb + tg];
            af[1] = Qs2[(mr + 8) * SQ2 + kb + tg];
            af[2] = Qs2[mr * SQ2       + kb + tg + 4];
            af[3] = Qs2[(mr + 8) * SQ2 + kb + tg + 4];
            #pragma unroll
            for (int ni = 0; ni < 3; ni++) {
                const int keyc = ng * 24 + ni * 8 + g;
                uint32_t bf[2];
                bf[0] = Ks2[(kb + tg) * SK2     + keyc];
                bf[1] = Ks2[(kb + tg + 4) * SK2 + keyc];
                mma_f16(sacc[ni], af, bf);
            }
        }
        // D-frag -> Sv
        #pragma unroll
        for (int ni = 0; ni < 3; ni++) {
            const int col = ng * 24 + ni * 8 + tg * 2;
            const int row = mt * 16 + g;
            *(float2*)(&Sv[row * SSV + col])       = make_float2(sacc[ni][0], sacc[ni][1]);
            *(float2*)(&Sv[(row + 8) * SSV + col]) = make_float2(sacc[ni][2], sacc[ni][3]);
        }
    }
    __syncthreads();

    // ---- Softmax + masking (R15 structure; scores read from Sv) ----
    const float inv_scale = 0.125f;
    #pragma unroll
    for (int qi = 0; qi < 4; qi++) {
        const int ql = 4 * w + qi;
        const int ig = t0 + ql;
        const int j0 = ig - PWH + l;
        const int j1 = j0 + 32;
        const int j2 = ig + PWH;
        const bool v0 = (j0 >= 0) && (j0 < PS) && (mask[b * PS + j0] != 0);
        const bool v1 = (j1 < PS) && (mask[b * PS + j1] != 0);
        const bool v2 = (j2 < PS) && (mask[b * PS + j2] != 0);

        float s0 = Sv[ql * SSV + ql + l];
        float s1 = Sv[ql * SSV + ql + l + 32];
        float s2 = Sv[ql * SSV + ql + 64];
        s0 = v0 ? s0 * inv_scale : -INFINITY;
        s1 = v1 ? s1 * inv_scale : -INFINITY;
        s2 = v2 ? s2 * inv_scale : -INFINITY;

        float m = fmaxf(fmaxf(s0, s1), s2);
        #pragma unroll
        for (int off = 16; off; off >>= 1)
            m = fmaxf(m, __shfl_xor_sync(0xffffffffu, m, off));

        const bool any = (m > -INFINITY);
        float e0 = (v0 && any) ? __expf(s0 - m) : 0.f;
        float e1 = (v1 && any) ? __expf(s1 - m) : 0.f;
        float e2 = (v2 && any) ? __expf(s2 - m) : 0.f;

        float ssum = e0 + e1;
        #pragma unroll
        for (int off = 16; off; off >>= 1)
            ssum += __shfl_xor_sync(0xffffffffu, ssum, off);
        ssum += e2;
        const float inv = any ? (1.0f / ssum) : 0.f;

        #pragma unroll
        for (int r = l; r < 68; r += 32) Pr4[w][qi][r] = 0.f;
        __syncwarp();
        Pr4[w][qi][qi + l]      = e0 * inv;
        Pr4[w][qi][qi + l + 32] = e1 * inv;
        if (l == 0) Pr4[w][qi][qi + 64] = e2 * inv;
        __syncwarp();
    }

    // ---- V pass (R15: fp32 global loads, band shared across 4 queries) ----
    const int r0g = t0 + 4 * w - PWH;
    float2 a0 = make_float2(0.f, 0.f), a1 = a0, a2 = a0, a3 = a0;

    #pragma unroll 4
    for (int r = 0; r < 68; r++) {
        int jg = r0g + r;
        jg = min(max(jg, 0), PS - 1);
        const float2 vv = *(const float2*)(v + base + (size_t)jg * PH + 2 * l);
        const float p0 = Pr4[w][0][r];
        const float p1 = Pr4[w][1][r];
        const float p2 = Pr4[w][2][r];
        const float p3 = Pr4[w][3][r];
        a0.x += p0 * vv.x; a0.y += p0 * vv.y;
        a1.x += p1 * vv.x; a1.y += p1 * vv.y;
        a2.x += p2 * vv.x; a2.y += p2 * vv.y;
        a3.x += p3 * vv.x; a3.y += p3 * vv.y;
    }

    {
        const int ig0 = t0 + 4 * w;
        uint32_t* o = (uint32_t*)(out + base + (size_t)ig0 * PH + 2 * l);
        o[0]          = pack_h2(a0.x, a0.y);
        o[PH / 2]     = pack_h2(a1.x, a1.y);
        o[PH]         = pack_h2(a2.x, a2.y);
        o[3 * PH / 2] = pack_h2(a3.x, a3.y);
    }
}

// ---------------------------------------------------------------------------
extern "C" void kernel_launch(void* const* d_in, const int* in_sizes, int n_in,
                              void* d_out, int out_size)
{
    const float* x    = (const float*)d_in[0];
    const int*   mask = (const int*)  d_in[1];
    const float* Wq   = (const float*)d_in[2];
    const float* bq   = (const float*)d_in[3];
    const float* Wk   = (const float*)d_in[4];
    const float* bk   = (const float*)d_in[5];
    const float* Wv   = (const float*)d_in[6];
    const float* bv   = (const float*)d_in[7];
    const float* Wo   = (const float*)d_in[8];
    const float* bo   = (const float*)d_in[9];
    float* out = (float*)d_out;

    float *qp, *kp, *vp;
    __half *xh, *ah;
    uint32_t *wqp, *wkp, *wvp, *wop;
    cudaGetSymbolAddress((void**)&qp,  g_q);
    cudaGetSymbolAddress((void**)&kp,  g_k);
    cudaGetSymbolAddress((void**)&vp,  g_v);
    cudaGetSymbolAddress((void**)&xh,  g_xh);
    cudaGetSymbolAddress((void**)&ah,  g_ah);
    cudaGetSymbolAddress((void**)&wqp, g_wqp);
    cudaGetSymbolAddress((void**)&wkp, g_wkp);
    cudaGetSymbolAddress((void**)&wvp, g_wvp);
    cudaGetSymbolAddress((void**)&wop, g_wop);

    // Pre-passes
    const int nx4 = SCR_ELEMS / 4;
    f32_to_f16_kernel<<<(nx4 + 255) / 256, 256>>>(x, xh, nx4);
    const int nw = PH * PH / 2;
    pack_w_kernel<<<nw / 256, 256>>>(Wq, wqp);
    pack_w_kernel<<<nw / 256, 256>>>(Wk, wkp);
    pack_w_kernel<<<nw / 256, 256>>>(Wv, wvp);
    pack_w_kernel<<<nw / 256, 256>>>(Wo, wop);

    dim3 ggrid(GN / 128, PM / 128);  // (8, 64)
    gemm_f16_db<<<ggrid, 256>>>(xh, wqp, bq, qp);
    gemm_f16_db<<<ggrid, 256>>>(xh, wkp, bk, kp);
    gemm_f16_db<<<ggrid, 256>>>(xh, wvp, bv, vp);

    attn_kernel<<<PB * PNH * (PS / 32), 256>>>(qp, kp, vp, mask, ah);

    gemm_f16_db<<<ggrid, 256>>>(ah, wop, bo, out);
}